// round 3
// baseline (speedup 1.0000x reference)
#include <cuda_runtime.h>
#include <math.h>

// Problem dims
#define BATCH 4096
#define AGENTS 32
#define NROWS (BATCH*AGENTS)      // 131072
#define OBS 128
#define HID 256
#define MSG 64
#define NH 4
#define DH 16
#define NACT 16

// ---------------- scratch (device globals; no allocation) ----------------
__device__ float g_Wemb[384*128];
__device__ float g_bemb[384];
__device__ float g_emb[(size_t)NROWS*384];   // [local(256) | intra(64) | inter(64)]
__device__ float g_qkv[(size_t)NROWS*768];   // 4 nets x 192
__device__ float g_atto[(size_t)NROWS*256];  // 4 nets x 64 (attn out, pre-Wo)
__device__ float g_mha[(size_t)NROWS*256];   // 4 nets x 64 (post-Wo)
__device__ float g_inter[(size_t)NROWS*64];  // inter_obs
__device__ float g_plogit[NROWS];            // pooling logits
__device__ float g_h1[(size_t)NROWS*256];
__device__ float g_h2[(size_t)NROWS*256];

// ---------------- helpers ----------------
__device__ __forceinline__ float softplusf(float x) {
    return x > 20.0f ? x : log1pf(__expf(x));
}

// ---------------- pack embedding weights [W_local; W_intra; W_inter] ----------------
__global__ void pack_emb_w(const float* __restrict__ Wl, const float* __restrict__ bl,
                           const float* __restrict__ Wi, const float* __restrict__ bi,
                           const float* __restrict__ Wt, const float* __restrict__ bt) {
    int idx = blockIdx.x * blockDim.x + threadIdx.x;
    if (idx < 384*128) {
        int row = idx >> 7, col = idx & 127;
        float v;
        if (row < 256)      v = Wl[row*128 + col];
        else if (row < 320) v = Wt[(row-256)*128 + col];   // W_intra -> cols 256..319
        else                v = Wi[(row-320)*128 + col];   // W_inter -> cols 320..383
        g_Wemb[idx] = v;
    }
    if (idx < 384) {
        g_bemb[idx] = (idx < 256) ? bl[idx] : (idx < 320 ? bt[idx-256] : bi[idx-320]);
    }
}

// ---------------- generic tiled SGEMM: Y[m][n] = epi(X[m,:K] . W[n,:K] + bias[n]) ----------------
// X row-major [*, ldx], W row-major [Mout, K], Y row-major [*, ldy].
// BM=128, BN=64, BK=32, 256 threads, 8x4 per-thread tile. K % 32 == 0.
template<int EPI>   // 0 = bias only, 1 = bias + tanh
__global__ __launch_bounds__(256) void gemm_bias(
    const float* __restrict__ X, int ldx,
    const float* __restrict__ W, const float* __restrict__ bias,
    float* __restrict__ Y, int ldy, int K)
{
    __shared__ float Xs[32][128];
    __shared__ float Ws[32][64];

    const int tid = threadIdx.x;
    const int tr = tid >> 4;         // 0..15 -> m sub-tile
    const int tc = tid & 15;         // 0..15 -> n sub-tile
    const int m0 = blockIdx.x * 128;
    const int n0 = blockIdx.y * 64;

    const int lxm = tid & 127;
    const int lxk = (tid >> 7) << 2;       // 0 or 4
    const int lwn = tid & 63;
    const int lwk = (tid >> 6) << 2;       // 0,4,8,12

    const float* Xp = X + (size_t)(m0 + lxm) * ldx + lxk;
    const float* Wp = W + (size_t)(n0 + lwn) * K + lwk;

    float acc[8][4];
#pragma unroll
    for (int i = 0; i < 8; i++)
#pragma unroll
        for (int j = 0; j < 4; j++) acc[i][j] = 0.0f;

    for (int k0 = 0; k0 < K; k0 += 32) {
#pragma unroll
        for (int kk = 0; kk < 32; kk += 8) {
            float4 v = *(const float4*)(Xp + k0 + kk);
            Xs[lxk+kk+0][lxm] = v.x; Xs[lxk+kk+1][lxm] = v.y;
            Xs[lxk+kk+2][lxm] = v.z; Xs[lxk+kk+3][lxm] = v.w;
        }
#pragma unroll
        for (int kk = 0; kk < 32; kk += 16) {
            float4 v = *(const float4*)(Wp + k0 + kk);
            Ws[lwk+kk+0][lwn] = v.x; Ws[lwk+kk+1][lwn] = v.y;
            Ws[lwk+kk+2][lwn] = v.z; Ws[lwk+kk+3][lwn] = v.w;
        }
        __syncthreads();
#pragma unroll
        for (int k = 0; k < 32; k++) {
            float4 xa = *(const float4*)&Xs[k][tr*8];
            float4 xb = *(const float4*)&Xs[k][tr*8 + 4];
            float4 wv = *(const float4*)&Ws[k][tc*4];
            float xr[8] = {xa.x, xa.y, xa.z, xa.w, xb.x, xb.y, xb.z, xb.w};
            float wr[4] = {wv.x, wv.y, wv.z, wv.w};
#pragma unroll
            for (int i = 0; i < 8; i++)
#pragma unroll
                for (int j = 0; j < 4; j++) acc[i][j] += xr[i] * wr[j];
        }
        __syncthreads();
    }

    float bb[4];
#pragma unroll
    for (int j = 0; j < 4; j++) bb[j] = bias[n0 + tc*4 + j];

#pragma unroll
    for (int i = 0; i < 8; i++) {
        int m = m0 + tr*8 + i;
        float4 o;
        float v0 = acc[i][0] + bb[0], v1 = acc[i][1] + bb[1];
        float v2 = acc[i][2] + bb[2], v3 = acc[i][3] + bb[3];
        if (EPI == 1) { v0 = tanhf(v0); v1 = tanhf(v1); v2 = tanhf(v2); v3 = tanhf(v3); }
        o.x = v0; o.y = v1; o.z = v2; o.w = v3;
        *(float4*)(Y + (size_t)m * ldy + n0 + tc*4) = o;
    }
}

// ---------------- attention core: per (b, net), 4 heads x 32 q-rows ----------------
__global__ __launch_bounds__(128) void attn_kernel(const float* __restrict__ qkv,
                                                   float* __restrict__ atto) {
    __shared__ float s[32][196];   // [agent][q(64)|k(64)|v(64)] padded
    const int b = blockIdx.x, net = blockIdx.y;
    const int tid = threadIdx.x;

    const float* base = qkv + (size_t)b * 32 * 768 + net * 192;
    for (int i = tid; i < 1536; i += 128) {
        int row = i / 48, col = (i % 48) * 4;
        float4 v = *(const float4*)(base + (size_t)row * 768 + col);
        s[row][col+0] = v.x; s[row][col+1] = v.y; s[row][col+2] = v.z; s[row][col+3] = v.w;
    }
    __syncthreads();

    const int h = tid >> 5, qi = tid & 31;
    float q[16];
#pragma unroll
    for (int d = 0; d < 16; d++) q[d] = s[qi][h*16 + d];

    float sc[32];
#pragma unroll 4
    for (int ki = 0; ki < 32; ki++) {
        float dot = 0.0f;
#pragma unroll
        for (int d = 0; d < 16; d++) dot += q[d] * s[ki][64 + h*16 + d];
        sc[ki] = dot * 0.25f;   // 1/sqrt(16)
    }
    float mx = sc[0];
#pragma unroll
    for (int ki = 1; ki < 32; ki++) mx = fmaxf(mx, sc[ki]);
    float sum = 0.0f;
#pragma unroll
    for (int ki = 0; ki < 32; ki++) { sc[ki] = __expf(sc[ki] - mx); sum += sc[ki]; }
    float rs = 1.0f / sum;

    float o[16];
#pragma unroll
    for (int j = 0; j < 16; j++) o[j] = 0.0f;
#pragma unroll 4
    for (int ki = 0; ki < 32; ki++) {
        float p = sc[ki];
#pragma unroll
        for (int j = 0; j < 16; j++) o[j] += p * s[ki][128 + h*16 + j];
    }
    float* op = atto + (size_t)(b*32 + qi) * 256 + net*64 + h*16;
#pragma unroll
    for (int j = 0; j < 16; j += 4) {
        float4 v; v.x = o[j]*rs; v.y = o[j+1]*rs; v.z = o[j+2]*rs; v.w = o[j+3]*rs;
        *(float4*)(op + j) = v;
    }
}

// ---------------- reparameterise + pooling logit ----------------
__global__ __launch_bounds__(64) void reparam_kernel(
    const float* __restrict__ eps_intra, const float* __restrict__ eps_inter,
    const float* __restrict__ att_w, const float* __restrict__ att_b)
{
    const int r = blockIdx.x, t = threadIdx.x;
    const float* mh = g_mha + (size_t)r * 256;

    float intra = mh[t] + softplusf(mh[64 + t] - 5.0f) * eps_intra[(size_t)r*64 + t];
    g_emb[(size_t)r*384 + 256 + t] = intra;

    float inter = mh[128 + t] + softplusf(mh[192 + t] - 5.0f) * eps_inter[(size_t)r*64 + t];
    g_inter[(size_t)r*64 + t] = inter;

    __shared__ float red[64];
    red[t] = inter * att_w[t];
    __syncthreads();
    for (int sft = 32; sft > 0; sft >>= 1) {
        if (t < sft) red[t] += red[t + sft];
        __syncthreads();
    }
    if (t == 0) g_plogit[r] = red[0] + att_b[0];
}

// ---------------- per-batch softmax pooling over agents ----------------
__global__ __launch_bounds__(64) void pool_kernel() {
    const int b = blockIdx.x, t = threadIdx.x;
    __shared__ float sl[32];
    if (t < 32) sl[t] = g_plogit[b*32 + t];
    __syncthreads();
    float mx = sl[0];
#pragma unroll
    for (int a = 1; a < 32; a++) mx = fmaxf(mx, sl[a]);
    float e[32]; float sum = 0.0f;
#pragma unroll
    for (int a = 0; a < 32; a++) { e[a] = __expf(sl[a] - mx); sum += e[a]; }
    float rs = 1.0f / sum;
    float pooled = 0.0f;
#pragma unroll
    for (int a = 0; a < 32; a++) pooled += e[a] * g_inter[(size_t)(b*32 + a)*64 + t];
    pooled *= rs;
#pragma unroll
    for (int a = 0; a < 32; a++) g_emb[(size_t)(b*32 + a)*384 + 320 + t] = pooled;
}

// ---------------- fused action/value head: 16 rows per block ----------------
__global__ __launch_bounds__(256) void head_kernel(
    const float* __restrict__ Wa, const float* __restrict__ ba,
    const float* __restrict__ Wv, const float* __restrict__ bv,
    float* __restrict__ out)
{
    __shared__ float sh[16][257];
    __shared__ float swa[16][257];
    __shared__ float swv[256];
    const int tid = threadIdx.x;
    const int r0 = blockIdx.x * 16;

    for (int i = tid; i < 1024; i += 256) {
        int row = i >> 6, col = (i & 63) << 2;
        float4 v = *(const float4*)(g_h2 + (size_t)(r0 + row) * 256 + col);
        sh[row][col+0] = v.x; sh[row][col+1] = v.y; sh[row][col+2] = v.z; sh[row][col+3] = v.w;
        float4 w = *(const float4*)(Wa + row * 256 + col);
        swa[row][col+0] = w.x; swa[row][col+1] = w.y; swa[row][col+2] = w.z; swa[row][col+3] = w.w;
    }
    if (tid < 64) *(float4*)&swv[tid*4] = *(const float4*)(Wv + tid*4);
    __syncthreads();

    const int r = tid >> 4, o = tid & 15;
    float acc = 0.0f;
#pragma unroll 8
    for (int k = 0; k < 256; k++) acc += sh[r][k] * swa[o][k];
    acc += ba[o];

    float vacc = 0.0f;
#pragma unroll
    for (int k = 0; k < 16; k++) vacc += sh[r][o*16 + k] * swv[o*16 + k];

    // log-softmax over the 16-lane group (lanes aligned: o = lane & 15)
    float mx = acc;
#pragma unroll
    for (int m = 8; m > 0; m >>= 1) mx = fmaxf(mx, __shfl_xor_sync(0xffffffffu, mx, m));
    float ex = __expf(acc - mx);
    float sum = ex;
#pragma unroll
    for (int m = 8; m > 0; m >>= 1) sum += __shfl_xor_sync(0xffffffffu, sum, m);
    float lse = mx + logf(sum);

    out[(size_t)(r0 + r) * 16 + o] = acc - lse;

    float vs = vacc;
#pragma unroll
    for (int m = 8; m > 0; m >>= 1) vs += __shfl_xor_sync(0xffffffffu, vs, m);
    if (o == 0) out[(size_t)NROWS * 16 + r0 + r] = vs + bv[0];
}

// ---------------- launch ----------------
extern "C" void kernel_launch(void* const* d_in, const int* in_sizes, int n_in,
                              void* d_out, int out_size) {
    const float* obs       = (const float*)d_in[0];
    const float* eps_intra = (const float*)d_in[1];
    const float* eps_inter = (const float*)d_in[2];
    const float* W_local   = (const float*)d_in[3];
    const float* b_local   = (const float*)d_in[4];
    const float* W_inter   = (const float*)d_in[5];
    const float* b_inter   = (const float*)d_in[6];
    const float* W_intra   = (const float*)d_in[7];
    const float* b_intra   = (const float*)d_in[8];
    const float* Wqkv      = (const float*)d_in[9];
    const float* bqkv      = (const float*)d_in[10];
    const float* Wo        = (const float*)d_in[11];
    const float* bo        = (const float*)d_in[12];
    const float* att_w     = (const float*)d_in[13];
    const float* att_b     = (const float*)d_in[14];
    const float* W1        = (const float*)d_in[15];
    const float* b1        = (const float*)d_in[16];
    const float* W2        = (const float*)d_in[17];
    const float* b2        = (const float*)d_in[18];
    const float* Wa        = (const float*)d_in[19];
    const float* ba        = (const float*)d_in[20];
    const float* Wv        = (const float*)d_in[21];
    const float* bv        = (const float*)d_in[22];
    float* out = (float*)d_out;

    float *p_emb, *p_qkv, *p_atto, *p_mha, *p_h1, *p_h2, *p_Wemb, *p_bemb;
    cudaGetSymbolAddress((void**)&p_emb,  g_emb);
    cudaGetSymbolAddress((void**)&p_qkv,  g_qkv);
    cudaGetSymbolAddress((void**)&p_atto, g_atto);
    cudaGetSymbolAddress((void**)&p_mha,  g_mha);
    cudaGetSymbolAddress((void**)&p_h1,   g_h1);
    cudaGetSymbolAddress((void**)&p_h2,   g_h2);
    cudaGetSymbolAddress((void**)&p_Wemb, g_Wemb);
    cudaGetSymbolAddress((void**)&p_bemb, g_bemb);

    const int MB = NROWS / 128;   // 1024

    // 1) pack embedding weights
    pack_emb_w<<<192, 256>>>(W_local, b_local, W_inter, b_inter, W_intra, b_intra);

    // 2) fused embeddings: [local | intra_e | inter_e] = tanh(obs @ Wemb^T + b)
    gemm_bias<1><<<dim3(MB, 6), 256>>>(obs, 128, p_Wemb, p_bemb, p_emb, 384, 128);

    // 3) qkv for nets 0,1 (intra_e) and 2,3 (inter_e)
    gemm_bias<0><<<dim3(MB, 6), 256>>>(p_emb + 256, 384, Wqkv,          bqkv,       p_qkv,       768, 64);
    gemm_bias<0><<<dim3(MB, 6), 256>>>(p_emb + 320, 384, Wqkv + 384*64, bqkv + 384, p_qkv + 384, 768, 64);

    // 4) attention core
    attn_kernel<<<dim3(BATCH, 4), 128>>>(p_qkv, p_atto);

    // 5) output projections Wo per net
    for (int i = 0; i < 4; i++)
        gemm_bias<0><<<dim3(MB, 1), 256>>>(p_atto + i*64, 256, Wo + i*64*64, bo + i*64,
                                           p_mha + i*64, 256, 64);

    // 6) reparameterise + pooling logits
    reparam_kernel<<<NROWS, 64>>>(eps_intra, eps_inter, att_w, att_b);

    // 7) softmax pooling over agents (writes pooled into emb cols 320..383)
    pool_kernel<<<BATCH, 64>>>();

    // 8) MLP
    gemm_bias<1><<<dim3(MB, 4), 256>>>(p_emb, 384, W1, b1, p_h1, 256, 384);
    gemm_bias<1><<<dim3(MB, 4), 256>>>(p_h1,  256, W2, b2, p_h2, 256, 256);

    // 9) fused action/value head with log-softmax
    head_kernel<<<NROWS/16, 256>>>(Wa, ba, Wv, bv, out);
}

// round 4
// speedup vs baseline: 2.0524x; 2.0524x over previous
#include <cuda_runtime.h>
#include <math.h>

#define BATCH 4096
#define AGENTS 32
#define NROWS (BATCH*AGENTS)      // 131072
#define NACT 16

// ---------------- scratch (device globals; no allocation) ----------------
__device__ float g_Wemb[384*128];
__device__ float g_bemb[384];
__device__ float g_emb[(size_t)NROWS*384];   // [local(256) | intra(64) | inter->pooled(64)]
__device__ float g_qkv[(size_t)NROWS*768];   // 4 nets x 192
__device__ float g_atto[(size_t)NROWS*256];  // 4 nets x 64 (attn out, pre-Wo)
__device__ float g_mha[(size_t)NROWS*256];   // 4 nets x 64 (post-Wo)
__device__ float g_inter[(size_t)NROWS*64];  // inter_obs
__device__ float g_plogit[NROWS];
__device__ float g_h1[(size_t)NROWS*256];
__device__ float g_h2[(size_t)NROWS*256];

__device__ __forceinline__ float softplusf(float x) {
    return x > 20.0f ? x : log1pf(__expf(x));
}
__device__ __forceinline__ unsigned rna_tf32(float x) {
    unsigned r; asm("cvt.rna.tf32.f32 %0, %1;" : "=r"(r) : "f"(x)); return r;
}
__device__ __forceinline__ void mma_tf32(float* c, const unsigned* a, unsigned b0, unsigned b1) {
    asm volatile("mma.sync.aligned.m16n8k8.row.col.f32.tf32.tf32.f32 "
                 "{%0,%1,%2,%3},{%4,%5,%6,%7},{%8,%9},{%0,%1,%2,%3};"
                 : "+f"(c[0]), "+f"(c[1]), "+f"(c[2]), "+f"(c[3])
                 : "r"(a[0]), "r"(a[1]), "r"(a[2]), "r"(a[3]), "r"(b0), "r"(b1));
}
__device__ __forceinline__ void cp16(unsigned s, const float* g) {
    asm volatile("cp.async.ca.shared.global [%0], [%1], 16;\n" :: "r"(s), "l"(g));
}

// ---------------- pack embedding weights [W_local; W_intra; W_inter] ----------------
__global__ void pack_emb_w(const float* __restrict__ Wl, const float* __restrict__ bl,
                           const float* __restrict__ Wi, const float* __restrict__ bi,
                           const float* __restrict__ Wt, const float* __restrict__ bt) {
    int idx = blockIdx.x * blockDim.x + threadIdx.x;
    if (idx < 384*128) {
        int row = idx >> 7, col = idx & 127;
        float v;
        if (row < 256)      v = Wl[row*128 + col];
        else if (row < 320) v = Wt[(row-256)*128 + col];
        else                v = Wi[(row-320)*128 + col];
        g_Wemb[idx] = v;
    }
    if (idx < 384)
        g_bemb[idx] = (idx < 256) ? bl[idx] : (idx < 320 ? bt[idx-256] : bi[idx-320]);
}

// ---------------- TF32 tensor-core GEMM: Y = epi(X[m,:K].W[n,:K] + bias[n]) ----------------
// BM=128, BN=64, BK=16, 256 thr, warps 4(m) x 2(n), warp tile 32x32.
// Smem rows padded to 20 floats -> conflict-free fragment loads.
template<int EPI>  // 0 = bias, 1 = bias + tanh
__global__ __launch_bounds__(256) void gemm_tc(
    const float* __restrict__ X, int ldx,
    const float* __restrict__ W, const float* __restrict__ bias,
    float* __restrict__ Y, int ldy, int K)
{
    __shared__ float Xs[2][128*20];
    __shared__ float Ws[2][64*20];

    const int tid = threadIdx.x;
    const int m0 = blockIdx.x * 128, n0 = blockIdx.y * 64;
    const int warp = tid >> 5, lane = tid & 31;
    const int wm = (warp & 3) * 32, wn = (warp >> 2) * 32;
    const int l4 = lane >> 2, l2 = lane & 3;

    // g2s assignments
    const int xm0 = tid >> 2, xkc = (tid & 3) << 2;       // X: rows tid/4 and tid/4+64
    const int wn0 = tid >> 2, wkc = xkc;                   // W: row tid/4

    unsigned xs0 = (unsigned)__cvta_generic_to_shared(&Xs[0][0]);
    unsigned ws0 = (unsigned)__cvta_generic_to_shared(&Ws[0][0]);

    float acc[2][4][4];
#pragma unroll
    for (int a = 0; a < 2; a++)
#pragma unroll
        for (int b = 0; b < 4; b++)
#pragma unroll
            for (int c = 0; c < 4; c++) acc[a][b][c] = 0.0f;

    const int nstage = K >> 4;

    // prologue: stage 0
    {
        cp16(xs0 + (xm0*20 + xkc)*4,        X + (size_t)(m0 + xm0)*ldx + xkc);
        cp16(xs0 + ((xm0+64)*20 + xkc)*4,   X + (size_t)(m0 + xm0 + 64)*ldx + xkc);
        cp16(ws0 + (wn0*20 + wkc)*4,        W + (size_t)(n0 + wn0)*K + wkc);
        asm volatile("cp.async.commit_group;\n");
    }

    for (int s = 0; s < nstage; s++) {
        if (s + 1 < nstage) {
            int k0 = (s + 1) << 4;
            unsigned xb = xs0 + ((s+1)&1) * 128*20*4;
            unsigned wb = ws0 + ((s+1)&1) * 64*20*4;
            cp16(xb + (xm0*20 + xkc)*4,      X + (size_t)(m0 + xm0)*ldx + k0 + xkc);
            cp16(xb + ((xm0+64)*20 + xkc)*4, X + (size_t)(m0 + xm0 + 64)*ldx + k0 + xkc);
            cp16(wb + (wn0*20 + wkc)*4,      W + (size_t)(n0 + wn0)*K + k0 + wkc);
            asm volatile("cp.async.commit_group;\n");
            asm volatile("cp.async.wait_group 1;\n");
        } else {
            asm volatile("cp.async.wait_group 0;\n");
        }
        __syncthreads();

        const float* Xb = &Xs[s & 1][0];
        const float* Wb = &Ws[s & 1][0];
#pragma unroll
        for (int k8 = 0; k8 < 16; k8 += 8) {
            unsigned afr[2][4];
#pragma unroll
            for (int mf = 0; mf < 2; mf++) {
                const float* ap = Xb + (wm + mf*16 + l4)*20 + k8 + l2;
                afr[mf][0] = rna_tf32(ap[0]);
                afr[mf][1] = rna_tf32(ap[8*20]);
                afr[mf][2] = rna_tf32(ap[4]);
                afr[mf][3] = rna_tf32(ap[8*20 + 4]);
            }
#pragma unroll
            for (int nf = 0; nf < 4; nf++) {
                const float* bp = Wb + (wn + nf*8 + l4)*20 + k8 + l2;
                unsigned b0 = rna_tf32(bp[0]);
                unsigned b1 = rna_tf32(bp[4]);
#pragma unroll
                for (int mf = 0; mf < 2; mf++)
                    mma_tf32(acc[mf][nf], afr[mf], b0, b1);
            }
        }
        __syncthreads();
    }

    // epilogue
#pragma unroll
    for (int nf = 0; nf < 4; nf++) {
        int col = n0 + wn + nf*8 + l2*2;
        float bb0 = bias[col], bb1 = bias[col + 1];
#pragma unroll
        for (int mf = 0; mf < 2; mf++) {
            int row = m0 + wm + mf*16 + l4;
            float v0 = acc[mf][nf][0] + bb0, v1 = acc[mf][nf][1] + bb1;
            float v2 = acc[mf][nf][2] + bb0, v3 = acc[mf][nf][3] + bb1;
            if (EPI == 1) { v0 = tanhf(v0); v1 = tanhf(v1); v2 = tanhf(v2); v3 = tanhf(v3); }
            float2 o01; o01.x = v0; o01.y = v1;
            float2 o23; o23.x = v2; o23.y = v3;
            *(float2*)(Y + (size_t)row * ldy + col) = o01;
            *(float2*)(Y + (size_t)(row + 8) * ldy + col) = o23;
        }
    }
}

// ---------------- attention core: per (b, net), 4 heads x 32 q-rows ----------------
__global__ __launch_bounds__(128) void attn_kernel(const float* __restrict__ qkv,
                                                   float* __restrict__ atto) {
    __shared__ float s[32][196];
    const int b = blockIdx.x, net = blockIdx.y;
    const int tid = threadIdx.x;

    const float* base = qkv + (size_t)b * 32 * 768 + net * 192;
    for (int i = tid; i < 1536; i += 128) {
        int row = i / 48, col = (i % 48) * 4;
        float4 v = *(const float4*)(base + (size_t)row * 768 + col);
        s[row][col+0] = v.x; s[row][col+1] = v.y; s[row][col+2] = v.z; s[row][col+3] = v.w;
    }
    __syncthreads();

    const int h = tid >> 5, qi = tid & 31;
    float q[16];
#pragma unroll
    for (int d = 0; d < 16; d++) q[d] = s[qi][h*16 + d];

    float sc[32];
#pragma unroll 4
    for (int ki = 0; ki < 32; ki++) {
        float dot = 0.0f;
#pragma unroll
        for (int d = 0; d < 16; d++) dot += q[d] * s[ki][64 + h*16 + d];
        sc[ki] = dot * 0.25f;
    }
    float mx = sc[0];
#pragma unroll
    for (int ki = 1; ki < 32; ki++) mx = fmaxf(mx, sc[ki]);
    float sum = 0.0f;
#pragma unroll
    for (int ki = 0; ki < 32; ki++) { sc[ki] = __expf(sc[ki] - mx); sum += sc[ki]; }
    float rs = 1.0f / sum;

    float o[16];
#pragma unroll
    for (int j = 0; j < 16; j++) o[j] = 0.0f;
#pragma unroll 4
    for (int ki = 0; ki < 32; ki++) {
        float p = sc[ki];
#pragma unroll
        for (int j = 0; j < 16; j++) o[j] += p * s[ki][128 + h*16 + j];
    }
    float* op = atto + (size_t)(b*32 + qi) * 256 + net*64 + h*16;
#pragma unroll
    for (int j = 0; j < 16; j += 4) {
        float4 v; v.x = o[j]*rs; v.y = o[j+1]*rs; v.z = o[j+2]*rs; v.w = o[j+3]*rs;
        *(float4*)(op + j) = v;
    }
}

// ---------------- reparameterise + pooling logit ----------------
__global__ __launch_bounds__(64) void reparam_kernel(
    const float* __restrict__ eps_intra, const float* __restrict__ eps_inter,
    const float* __restrict__ att_w, const float* __restrict__ att_b)
{
    const int r = blockIdx.x, t = threadIdx.x;
    const float* mh = g_mha + (size_t)r * 256;

    float intra = mh[t] + softplusf(mh[64 + t] - 5.0f) * eps_intra[(size_t)r*64 + t];
    g_emb[(size_t)r*384 + 256 + t] = intra;

    float inter = mh[128 + t] + softplusf(mh[192 + t] - 5.0f) * eps_inter[(size_t)r*64 + t];
    g_inter[(size_t)r*64 + t] = inter;

    __shared__ float red[64];
    red[t] = inter * att_w[t];
    __syncthreads();
    for (int sft = 32; sft > 0; sft >>= 1) {
        if (t < sft) red[t] += red[t + sft];
        __syncthreads();
    }
    if (t == 0) g_plogit[r] = red[0] + att_b[0];
}

// ---------------- per-batch softmax pooling over agents ----------------
__global__ __launch_bounds__(64) void pool_kernel() {
    const int b = blockIdx.x, t = threadIdx.x;
    __shared__ float sl[32];
    if (t < 32) sl[t] = g_plogit[b*32 + t];
    __syncthreads();
    float mx = sl[0];
#pragma unroll
    for (int a = 1; a < 32; a++) mx = fmaxf(mx, sl[a]);
    float e[32]; float sum = 0.0f;
#pragma unroll
    for (int a = 0; a < 32; a++) { e[a] = __expf(sl[a] - mx); sum += e[a]; }
    float rs = 1.0f / sum;
    float pooled = 0.0f;
#pragma unroll
    for (int a = 0; a < 32; a++) pooled += e[a] * g_inter[(size_t)(b*32 + a)*64 + t];
    pooled *= rs;
#pragma unroll
    for (int a = 0; a < 32; a++) g_emb[(size_t)(b*32 + a)*384 + 320 + t] = pooled;
}

// ---------------- fused action/value head: 16 rows per block ----------------
__global__ __launch_bounds__(256) void head_kernel(
    const float* __restrict__ Wa, const float* __restrict__ ba,
    const float* __restrict__ Wv, const float* __restrict__ bv,
    float* __restrict__ out)
{
    __shared__ float sh[16][257];
    __shared__ float swa[16][257];
    __shared__ float swv[256];
    const int tid = threadIdx.x;
    const int r0 = blockIdx.x * 16;

    for (int i = tid; i < 1024; i += 256) {
        int row = i >> 6, col = (i & 63) << 2;
        float4 v = *(const float4*)(g_h2 + (size_t)(r0 + row) * 256 + col);
        sh[row][col+0] = v.x; sh[row][col+1] = v.y; sh[row][col+2] = v.z; sh[row][col+3] = v.w;
        float4 w = *(const float4*)(Wa + row * 256 + col);
        swa[row][col+0] = w.x; swa[row][col+1] = w.y; swa[row][col+2] = w.z; swa[row][col+3] = w.w;
    }
    if (tid < 64) *(float4*)&swv[tid*4] = *(const float4*)(Wv + tid*4);
    __syncthreads();

    const int r = tid >> 4, o = tid & 15;
    float acc = 0.0f;
#pragma unroll 8
    for (int k = 0; k < 256; k++) acc += sh[r][k] * swa[o][k];
    acc += ba[o];

    float vacc = 0.0f;
#pragma unroll
    for (int k = 0; k < 16; k++) vacc += sh[r][o*16 + k] * swv[o*16 + k];

    float mx = acc;
#pragma unroll
    for (int m = 8; m > 0; m >>= 1) mx = fmaxf(mx, __shfl_xor_sync(0xffffffffu, mx, m));
    float ex = __expf(acc - mx);
    float sum = ex;
#pragma unroll
    for (int m = 8; m > 0; m >>= 1) sum += __shfl_xor_sync(0xffffffffu, sum, m);
    float lse = mx + logf(sum);

    out[(size_t)(r0 + r) * 16 + o] = acc - lse;

    float vs = vacc;
#pragma unroll
    for (int m = 8; m > 0; m >>= 1) vs += __shfl_xor_sync(0xffffffffu, vs, m);
    if (o == 0) out[(size_t)NROWS * 16 + r0 + r] = vs + bv[0];
}

// ---------------- launch ----------------
extern "C" void kernel_launch(void* const* d_in, const int* in_sizes, int n_in,
                              void* d_out, int out_size) {
    const float* obs       = (const float*)d_in[0];
    const float* eps_intra = (const float*)d_in[1];
    const float* eps_inter = (const float*)d_in[2];
    const float* W_local   = (const float*)d_in[3];
    const float* b_local   = (const float*)d_in[4];
    const float* W_inter   = (const float*)d_in[5];
    const float* b_inter   = (const float*)d_in[6];
    const float* W_intra   = (const float*)d_in[7];
    const float* b_intra   = (const float*)d_in[8];
    const float* Wqkv      = (const float*)d_in[9];
    const float* bqkv      = (const float*)d_in[10];
    const float* Wo        = (const float*)d_in[11];
    const float* bo        = (const float*)d_in[12];
    const float* att_w     = (const float*)d_in[13];
    const float* att_b     = (const float*)d_in[14];
    const float* W1        = (const float*)d_in[15];
    const float* b1        = (const float*)d_in[16];
    const float* W2        = (const float*)d_in[17];
    const float* b2        = (const float*)d_in[18];
    const float* Wa        = (const float*)d_in[19];
    const float* ba        = (const float*)d_in[20];
    const float* Wv        = (const float*)d_in[21];
    const float* bv        = (const float*)d_in[22];
    float* out = (float*)d_out;

    float *p_emb, *p_qkv, *p_atto, *p_mha, *p_h1, *p_h2, *p_Wemb, *p_bemb;
    cudaGetSymbolAddress((void**)&p_emb,  g_emb);
    cudaGetSymbolAddress((void**)&p_qkv,  g_qkv);
    cudaGetSymbolAddress((void**)&p_atto, g_atto);
    cudaGetSymbolAddress((void**)&p_mha,  g_mha);
    cudaGetSymbolAddress((void**)&p_h1,   g_h1);
    cudaGetSymbolAddress((void**)&p_h2,   g_h2);
    cudaGetSymbolAddress((void**)&p_Wemb, g_Wemb);
    cudaGetSymbolAddress((void**)&p_bemb, g_bemb);

    const int MB = NROWS / 128;   // 1024

    pack_emb_w<<<192, 256>>>(W_local, b_local, W_inter, b_inter, W_intra, b_intra);

    // embeddings: [local | intra_e | inter_e] = tanh(obs @ Wemb^T + b)
    gemm_tc<1><<<dim3(MB, 6), 256>>>(obs, 128, p_Wemb, p_bemb, p_emb, 384, 128);

    // qkv for nets 0,1 (from intra_e) and 2,3 (from inter_e)
    gemm_tc<0><<<dim3(MB, 6), 256>>>(p_emb + 256, 384, Wqkv,          bqkv,       p_qkv,       768, 64);
    gemm_tc<0><<<dim3(MB, 6), 256>>>(p_emb + 320, 384, Wqkv + 384*64, bqkv + 384, p_qkv + 384, 768, 64);

    attn_kernel<<<dim3(BATCH, 4), 128>>>(p_qkv, p_atto);

    for (int i = 0; i < 4; i++)
        gemm_tc<0><<<dim3(MB, 1), 256>>>(p_atto + i*64, 256, Wo + i*64*64, bo + i*64,
                                         p_mha + i*64, 256, 64);

    reparam_kernel<<<NROWS, 64>>>(eps_intra, eps_inter, att_w, att_b);
    pool_kernel<<<BATCH, 64>>>();

    gemm_tc<1><<<dim3(MB, 4), 256>>>(p_emb, 384, W1, b1, p_h1, 256, 384);
    gemm_tc<1><<<dim3(MB, 4), 256>>>(p_h1,  256, W2, b2, p_h2, 256, 256);

    head_kernel<<<NROWS/16, 256>>>(Wa, ba, Wv, bv, out);
}

// round 5
// speedup vs baseline: 2.2839x; 1.1128x over previous
#include <cuda_runtime.h>
#include <math.h>

#define BATCH 4096
#define AGENTS 32
#define NROWS (BATCH*AGENTS)      // 131072
#define NACT 16

// ---------------- scratch (device globals; no allocation) ----------------
__device__ float g_Wemb[384*128];
__device__ float g_bemb[384];
__device__ float g_Wqkv[768*64];
__device__ float g_Wo[4*64*64];
__device__ float g_W1[256*384];
__device__ float g_W2[256*256];
__device__ float g_emb[(size_t)NROWS*384];   // [local(256) | intra(64) | inter->pooled(64)]
__device__ float g_qkv[(size_t)NROWS*768];   // 4 nets x 192
__device__ float g_atto[(size_t)NROWS*256];  // 4 nets x 64 (attn out, pre-Wo)
__device__ float g_mha[(size_t)NROWS*256];   // 4 nets x 64 (post-Wo)
__device__ float g_inter[(size_t)NROWS*64];  // inter_obs
__device__ float g_plogit[NROWS];
__device__ float g_h1[(size_t)NROWS*256];
__device__ float g_h2[(size_t)NROWS*256];

__device__ __forceinline__ float softplusf(float x) {
    return x > 20.0f ? x : log1pf(__expf(x));
}
__device__ __forceinline__ unsigned rna_tf32(float x) {
    unsigned r; asm("cvt.rna.tf32.f32 %0, %1;" : "=r"(r) : "f"(x)); return r;
}
__device__ __forceinline__ float rndf(float x) {      // round fp32 -> nearest tf32 value
    return __uint_as_float(rna_tf32(x));
}
__device__ __forceinline__ void mma_tf32(float* c, const unsigned* a, unsigned b0, unsigned b1) {
    asm volatile("mma.sync.aligned.m16n8k8.row.col.f32.tf32.tf32.f32 "
                 "{%0,%1,%2,%3},{%4,%5,%6,%7},{%8,%9},{%0,%1,%2,%3};"
                 : "+f"(c[0]), "+f"(c[1]), "+f"(c[2]), "+f"(c[3])
                 : "r"(a[0]), "r"(a[1]), "r"(a[2]), "r"(a[3]), "r"(b0), "r"(b1));
}
__device__ __forceinline__ void cp16(unsigned s, const float* g) {
    asm volatile("cp.async.ca.shared.global [%0], [%1], 16;\n" :: "r"(s), "l"(g));
}

// ---------------- pack + tf32-round all weights ----------------
__global__ void pack_w(const float* __restrict__ Wl, const float* __restrict__ bl,
                       const float* __restrict__ Wi, const float* __restrict__ bi,
                       const float* __restrict__ Wt, const float* __restrict__ bt,
                       const float* __restrict__ Wqkv, const float* __restrict__ Wo,
                       const float* __restrict__ W1, const float* __restrict__ W2) {
    int idx = blockIdx.x * blockDim.x + threadIdx.x;
    if (idx < 384*128) {
        int row = idx >> 7, col = idx & 127;
        float v;
        if (row < 256)      v = Wl[row*128 + col];
        else if (row < 320) v = Wt[(row-256)*128 + col];
        else                v = Wi[(row-320)*128 + col];
        g_Wemb[idx] = rndf(v);
    }
    if (idx < 768*64)  g_Wqkv[idx] = rndf(Wqkv[idx]);
    if (idx < 4*64*64) g_Wo[idx]   = rndf(Wo[idx]);
    if (idx < 256*384) g_W1[idx]   = rndf(W1[idx]);
    if (idx < 256*256) g_W2[idx]   = rndf(W2[idx]);
    if (idx < 384)
        g_bemb[idx] = (idx < 256) ? bl[idx] : (idx < 320 ? bt[idx-256] : bi[idx-320]);
}

// ---------------- TF32 tensor-core GEMM ----------------
// Y = epi(X[m,:K] . W[n,:K] + bias[n]).  BM=128, BN in {128,64}, BK=16.
// 256 thr. BN=128: warps 2(m)x4(n), warp tile 64x32. BN=64: warps 4x2, tile 32x32.
// W must be pre-rounded to tf32. X pre-rounded unless CVTX=1.
// blockIdx.z batches independent GEMMs via bsX/bsW/bsB/bsY strides.
template<int BN, int EPI, int CVTX>   // EPI: 0 = bias, 1 = bias + tanh + tf32-round
__global__ __launch_bounds__(256) void gemm_tc(
    const float* __restrict__ X, int ldx,
    const float* __restrict__ W, const float* __restrict__ bias,
    float* __restrict__ Y, int ldy, int K,
    int bsX, int bsW, int bsB, int bsY)
{
    constexpr int WM = (BN == 128) ? 2 : 4;       // warps along m
    constexpr int MF = (BN == 128) ? 4 : 2;       // m16 fragments per warp
    __shared__ float Xs[2][128*20];
    __shared__ float Ws[2][BN*20];

    const int z = blockIdx.z;
    X += (size_t)z * bsX; W += (size_t)z * bsW; bias += (size_t)z * bsB; Y += (size_t)z * bsY;

    const int tid = threadIdx.x;
    const int m0 = blockIdx.x * 128, n0 = blockIdx.y * BN;
    const int warp = tid >> 5, lane = tid & 31;
    const int wm = (warp % WM) * (MF*16), wn = (warp / WM) * 32;
    const int l4 = lane >> 2, l2 = lane & 3;

    const int xm0 = tid >> 2, xkc = (tid & 3) << 2;

    unsigned xs0 = (unsigned)__cvta_generic_to_shared(&Xs[0][0]);
    unsigned ws0 = (unsigned)__cvta_generic_to_shared(&Ws[0][0]);

    float acc[MF][4][4];
#pragma unroll
    for (int a = 0; a < MF; a++)
#pragma unroll
        for (int b = 0; b < 4; b++)
#pragma unroll
            for (int c = 0; c < 4; c++) acc[a][b][c] = 0.0f;

    const int nstage = K >> 4;

    // prologue: stage 0
    cp16(xs0 + (xm0*20 + xkc)*4,       X + (size_t)(m0 + xm0)*ldx + xkc);
    cp16(xs0 + ((xm0+64)*20 + xkc)*4,  X + (size_t)(m0 + xm0 + 64)*ldx + xkc);
    cp16(ws0 + (xm0*20 + xkc)*4,       W + (size_t)(n0 + xm0)*K + xkc);
    if (BN == 128)
        cp16(ws0 + ((xm0+64)*20 + xkc)*4, W + (size_t)(n0 + xm0 + 64)*K + xkc);
    asm volatile("cp.async.commit_group;\n");

    for (int s = 0; s < nstage; s++) {
        if (s + 1 < nstage) {
            int k0 = (s + 1) << 4;
            unsigned xb = xs0 + ((s+1)&1) * 128*20*4;
            unsigned wb = ws0 + ((s+1)&1) * BN*20*4;
            cp16(xb + (xm0*20 + xkc)*4,      X + (size_t)(m0 + xm0)*ldx + k0 + xkc);
            cp16(xb + ((xm0+64)*20 + xkc)*4, X + (size_t)(m0 + xm0 + 64)*ldx + k0 + xkc);
            cp16(wb + (xm0*20 + xkc)*4,      W + (size_t)(n0 + xm0)*K + k0 + xkc);
            if (BN == 128)
                cp16(wb + ((xm0+64)*20 + xkc)*4, W + (size_t)(n0 + xm0 + 64)*K + k0 + xkc);
            asm volatile("cp.async.commit_group;\n");
            asm volatile("cp.async.wait_group 1;\n");
        } else {
            asm volatile("cp.async.wait_group 0;\n");
        }
        __syncthreads();

        const float* Xb = &Xs[s & 1][0];
        const float* Wb = &Ws[s & 1][0];
#pragma unroll
        for (int k8 = 0; k8 < 16; k8 += 8) {
            unsigned afr[MF][4];
#pragma unroll
            for (int mf = 0; mf < MF; mf++) {
                const float* ap = Xb + (wm + mf*16 + l4)*20 + k8 + l2;
                if (CVTX) {
                    afr[mf][0] = rna_tf32(ap[0]);
                    afr[mf][1] = rna_tf32(ap[8*20]);
                    afr[mf][2] = rna_tf32(ap[4]);
                    afr[mf][3] = rna_tf32(ap[8*20 + 4]);
                } else {
                    afr[mf][0] = *(const unsigned*)&ap[0];
                    afr[mf][1] = *(const unsigned*)&ap[8*20];
                    afr[mf][2] = *(const unsigned*)&ap[4];
                    afr[mf][3] = *(const unsigned*)&ap[8*20 + 4];
                }
            }
#pragma unroll
            for (int nf = 0; nf < 4; nf++) {
                const float* bp = Wb + (wn + nf*8 + l4)*20 + k8 + l2;
                unsigned b0 = *(const unsigned*)&bp[0];
                unsigned b1 = *(const unsigned*)&bp[4];
#pragma unroll
                for (int mf = 0; mf < MF; mf++)
                    mma_tf32(acc[mf][nf], afr[mf], b0, b1);
            }
        }
        __syncthreads();
    }

    // epilogue
#pragma unroll
    for (int nf = 0; nf < 4; nf++) {
        int col = n0 + wn + nf*8 + l2*2;
        float bb0 = bias[col], bb1 = bias[col + 1];
#pragma unroll
        for (int mf = 0; mf < MF; mf++) {
            int row = m0 + wm + mf*16 + l4;
            float v0 = acc[mf][nf][0] + bb0, v1 = acc[mf][nf][1] + bb1;
            float v2 = acc[mf][nf][2] + bb0, v3 = acc[mf][nf][3] + bb1;
            if (EPI == 1) {
                v0 = rndf(tanhf(v0)); v1 = rndf(tanhf(v1));
                v2 = rndf(tanhf(v2)); v3 = rndf(tanhf(v3));
            }
            float2 o01; o01.x = v0; o01.y = v1;
            float2 o23; o23.x = v2; o23.y = v3;
            *(float2*)(Y + (size_t)row * ldy + col) = o01;
            *(float2*)(Y + (size_t)(row + 8) * ldy + col) = o23;
        }
    }
}

// ---------------- attention core: per (b, net), 4 heads x 32 q-rows ----------------
__global__ __launch_bounds__(128) void attn_kernel(const float* __restrict__ qkv,
                                                   float* __restrict__ atto) {
    __shared__ float s[32][196];
    const int b = blockIdx.x, net = blockIdx.y;
    const int tid = threadIdx.x;

    const float* base = qkv + (size_t)b * 32 * 768 + net * 192;
    for (int i = tid; i < 1536; i += 128) {
        int row = i / 48, col = (i % 48) * 4;
        float4 v = *(const float4*)(base + (size_t)row * 768 + col);
        s[row][col+0] = v.x; s[row][col+1] = v.y; s[row][col+2] = v.z; s[row][col+3] = v.w;
    }
    __syncthreads();

    const int h = tid >> 5, qi = tid & 31;
    float q[16];
#pragma unroll
    for (int d = 0; d < 16; d++) q[d] = s[qi][h*16 + d];

    float sc[32];
#pragma unroll 4
    for (int ki = 0; ki < 32; ki++) {
        float dot = 0.0f;
#pragma unroll
        for (int d = 0; d < 16; d++) dot += q[d] * s[ki][64 + h*16 + d];
        sc[ki] = dot * 0.25f;
    }
    float mx = sc[0];
#pragma unroll
    for (int ki = 1; ki < 32; ki++) mx = fmaxf(mx, sc[ki]);
    float sum = 0.0f;
#pragma unroll
    for (int ki = 0; ki < 32; ki++) { sc[ki] = __expf(sc[ki] - mx); sum += sc[ki]; }
    float rs = 1.0f / sum;

    float o[16];
#pragma unroll
    for (int j = 0; j < 16; j++) o[j] = 0.0f;
#pragma unroll 4
    for (int ki = 0; ki < 32; ki++) {
        float p = sc[ki];
#pragma unroll
        for (int j = 0; j < 16; j++) o[j] += p * s[ki][128 + h*16 + j];
    }
    float* op = atto + (size_t)(b*32 + qi) * 256 + net*64 + h*16;
#pragma unroll
    for (int j = 0; j < 16; j += 4) {
        float4 v;
        v.x = rndf(o[j]*rs);   v.y = rndf(o[j+1]*rs);
        v.z = rndf(o[j+2]*rs); v.w = rndf(o[j+3]*rs);
        *(float4*)(op + j) = v;
    }
}

// ---------------- reparameterise + pooling logit (warp per row) ----------------
__global__ __launch_bounds__(256) void reparam_kernel(
    const float* __restrict__ eps_intra, const float* __restrict__ eps_inter,
    const float* __restrict__ att_w, const float* __restrict__ att_b)
{
    const int warp = threadIdx.x >> 5, lane = threadIdx.x & 31;
    const int r = blockIdx.x * 8 + warp;
    const float* mh = g_mha + (size_t)r * 256;

    float part = 0.0f;
#pragma unroll
    for (int j = 0; j < 2; j++) {
        int c = lane + j*32;
        float intra = mh[c] + softplusf(mh[64 + c] - 5.0f) * eps_intra[(size_t)r*64 + c];
        g_emb[(size_t)r*384 + 256 + c] = rndf(intra);
        float inter = mh[128 + c] + softplusf(mh[192 + c] - 5.0f) * eps_inter[(size_t)r*64 + c];
        g_inter[(size_t)r*64 + c] = inter;
        part += inter * att_w[c];
    }
#pragma unroll
    for (int m = 16; m > 0; m >>= 1) part += __shfl_xor_sync(0xffffffffu, part, m);
    if (lane == 0) g_plogit[r] = part + att_b[0];
}

// ---------------- per-batch softmax pooling over agents ----------------
__global__ __launch_bounds__(64) void pool_kernel() {
    const int b = blockIdx.x, t = threadIdx.x;
    __shared__ float sl[32];
    if (t < 32) sl[t] = g_plogit[b*32 + t];
    __syncthreads();
    float mx = sl[0];
#pragma unroll
    for (int a = 1; a < 32; a++) mx = fmaxf(mx, sl[a]);
    float e[32]; float sum = 0.0f;
#pragma unroll
    for (int a = 0; a < 32; a++) { e[a] = __expf(sl[a] - mx); sum += e[a]; }
    float rs = 1.0f / sum;
    float pooled = 0.0f;
#pragma unroll
    for (int a = 0; a < 32; a++) pooled += e[a] * g_inter[(size_t)(b*32 + a)*64 + t];
    pooled = rndf(pooled * rs);
#pragma unroll
    for (int a = 0; a < 32; a++) g_emb[(size_t)(b*32 + a)*384 + 320 + t] = pooled;
}

// ---------------- fused action/value head: 16 rows per block (float4 smem) ----------------
__global__ __launch_bounds__(256) void head_kernel(
    const float* __restrict__ Wa, const float* __restrict__ ba,
    const float* __restrict__ Wv, const float* __restrict__ bv,
    float* __restrict__ out)
{
    __shared__ float4 sh4[16][65];
    __shared__ float4 swa4[16][65];
    __shared__ float4 swv4[64];
    const int tid = threadIdx.x;
    const int r0 = blockIdx.x * 16;

    for (int i = tid; i < 1024; i += 256) {
        int row = i >> 6, c4 = i & 63;
        sh4[row][c4]  = *(const float4*)(g_h2 + (size_t)(r0 + row) * 256 + c4*4);
        swa4[row][c4] = *(const float4*)(Wa + row * 256 + c4*4);
    }
    if (tid < 64) swv4[tid] = *(const float4*)(Wv + tid*4);
    __syncthreads();

    const int r = tid >> 4, o = tid & 15;
    float acc = 0.0f;
#pragma unroll 8
    for (int k = 0; k < 64; k++) {
        float4 h = sh4[r][k], w = swa4[o][k];
        acc += h.x*w.x + h.y*w.y + h.z*w.z + h.w*w.w;
    }
    acc += ba[o];

    float vacc = 0.0f;
#pragma unroll
    for (int k = 0; k < 4; k++) {
        float4 h = sh4[r][o*4 + k], w = swv4[o*4 + k];
        vacc += h.x*w.x + h.y*w.y + h.z*w.z + h.w*w.w;
    }

    float mx = acc;
#pragma unroll
    for (int m = 8; m > 0; m >>= 1) mx = fmaxf(mx, __shfl_xor_sync(0xffffffffu, mx, m));
    float ex = __expf(acc - mx);
    float sum = ex;
#pragma unroll
    for (int m = 8; m > 0; m >>= 1) sum += __shfl_xor_sync(0xffffffffu, sum, m);
    float lse = mx + logf(sum);

    out[(size_t)(r0 + r) * 16 + o] = acc - lse;

    float vs = vacc;
#pragma unroll
    for (int m = 8; m > 0; m >>= 1) vs += __shfl_xor_sync(0xffffffffu, vs, m);
    if (o == 0) out[(size_t)NROWS * 16 + r0 + r] = vs + bv[0];
}

// ---------------- launch ----------------
extern "C" void kernel_launch(void* const* d_in, const int* in_sizes, int n_in,
                              void* d_out, int out_size) {
    const float* obs       = (const float*)d_in[0];
    const float* eps_intra = (const float*)d_in[1];
    const float* eps_inter = (const float*)d_in[2];
    const float* W_local   = (const float*)d_in[3];
    const float* b_local   = (const float*)d_in[4];
    const float* W_inter   = (const float*)d_in[5];
    const float* b_inter   = (const float*)d_in[6];
    const float* W_intra   = (const float*)d_in[7];
    const float* b_intra   = (const float*)d_in[8];
    const float* Wqkv      = (const float*)d_in[9];
    const float* bqkv      = (const float*)d_in[10];
    const float* Wo        = (const float*)d_in[11];
    const float* bo        = (const float*)d_in[12];
    const float* att_w     = (const float*)d_in[13];
    const float* att_b     = (const float*)d_in[14];
    const float* W1        = (const float*)d_in[15];
    const float* b1        = (const float*)d_in[16];
    const float* W2        = (const float*)d_in[17];
    const float* b2        = (const float*)d_in[18];
    const float* Wa        = (const float*)d_in[19];
    const float* ba        = (const float*)d_in[20];
    const float* Wv        = (const float*)d_in[21];
    const float* bv        = (const float*)d_in[22];
    float* out = (float*)d_out;

    float *p_emb, *p_qkv, *p_atto, *p_mha, *p_h1, *p_h2;
    float *p_Wemb, *p_bemb, *p_Wqkv, *p_Wo, *p_W1, *p_W2;
    cudaGetSymbolAddress((void**)&p_emb,  g_emb);
    cudaGetSymbolAddress((void**)&p_qkv,  g_qkv);
    cudaGetSymbolAddress((void**)&p_atto, g_atto);
    cudaGetSymbolAddress((void**)&p_mha,  g_mha);
    cudaGetSymbolAddress((void**)&p_h1,   g_h1);
    cudaGetSymbolAddress((void**)&p_h2,   g_h2);
    cudaGetSymbolAddress((void**)&p_Wemb, g_Wemb);
    cudaGetSymbolAddress((void**)&p_bemb, g_bemb);
    cudaGetSymbolAddress((void**)&p_Wqkv, g_Wqkv);
    cudaGetSymbolAddress((void**)&p_Wo,   g_Wo);
    cudaGetSymbolAddress((void**)&p_W1,   g_W1);
    cudaGetSymbolAddress((void**)&p_W2,   g_W2);

    const int MB = NROWS / 128;   // 1024

    // 1) pack + round all weights
    pack_w<<<384, 256>>>(W_local, b_local, W_inter, b_inter, W_intra, b_intra,
                         Wqkv, Wo, W1, W2);

    // 2) embeddings: [local | intra_e | inter_e] = round(tanh(obs @ Wemb^T + b))
    gemm_tc<128,1,1><<<dim3(MB, 3, 1), 256>>>(obs, 128, p_Wemb, p_bemb, p_emb, 384, 128,
                                              0, 0, 0, 0);

    // 3) qkv: nets 0,1 from intra_e; nets 2,3 from inter_e
    gemm_tc<128,0,0><<<dim3(MB, 3, 1), 256>>>(p_emb + 256, 384, p_Wqkv, bqkv,
                                              p_qkv, 768, 64, 0, 0, 0, 0);
    gemm_tc<128,0,0><<<dim3(MB, 3, 1), 256>>>(p_emb + 320, 384, p_Wqkv + 384*64, bqkv + 384,
                                              p_qkv + 384, 768, 64, 0, 0, 0, 0);

    // 4) attention core (rounds atto)
    attn_kernel<<<dim3(BATCH, 4), 128>>>(p_qkv, p_atto);

    // 5) Wo projections: 4 nets batched on blockIdx.z
    gemm_tc<64,0,0><<<dim3(MB, 1, 4), 256>>>(p_atto, 256, p_Wo, bo, p_mha, 256, 64,
                                             64, 64*64, 64, 64);

    // 6) reparameterise + pooling logits
    reparam_kernel<<<NROWS/8, 256>>>(eps_intra, eps_inter, att_w, att_b);
    pool_kernel<<<BATCH, 64>>>();

    // 7) MLP
    gemm_tc<128,1,0><<<dim3(MB, 2, 1), 256>>>(p_emb, 384, p_W1, b1, p_h1, 256, 384,
                                              0, 0, 0, 0);
    gemm_tc<128,1,0><<<dim3(MB, 2, 1), 256>>>(p_h1, 256, p_W2, b2, p_h2, 256, 256,
                                              0, 0, 0, 0);

    // 8) fused action/value head with log-softmax
    head_kernel<<<NROWS/16, 256>>>(Wa, ba, Wv, bv, out);
}